// round 1
// baseline (speedup 1.0000x reference)
#include <cuda_runtime.h>

#define K_DIM   784
#define H_DIM   1024
#define O_DIM   10
#define B_SIZE  128
#define T_STEPS 200
#define M_TOTAL (B_SIZE * T_STEPS)   // 25600
#define BETA    0.95f

// Scratch for precomputed layer-1 currents: cur1[b*T+t][h]
__device__ float g_cur1[(size_t)M_TOTAL * H_DIM];

// ---------------------------------------------------------------------------
// GEMM1: C[M, H] = A[M, K] @ W[H, K]^T + bias[H]
// BM=128, BN=128, BK=8, 256 threads, 8x8 per thread. Pure fp32.
// ---------------------------------------------------------------------------
__global__ __launch_bounds__(256, 2) void gemm1_kernel(
    const float* __restrict__ A,
    const float* __restrict__ W,
    const float* __restrict__ bias)
{
    constexpr int BM = 128, BN = 128, BK = 8;
    __shared__ float As[BK][BM + 4];
    __shared__ float Bs[BK][BN + 4];

    const int bm  = blockIdx.y * BM;
    const int bn  = blockIdx.x * BN;
    const int tid = threadIdx.x;
    const int tr  = tid >> 4;          // 0..15 (row group)
    const int tc  = tid & 15;          // 0..15 (col group)
    const int lrow = tid >> 1;         // 0..127
    const int lcol = (tid & 1) << 2;   // 0 or 4

    const float* Aptr = A + (size_t)(bm + lrow) * K_DIM + lcol;
    const float* Wptr = W + (size_t)(bn + lrow) * K_DIM + lcol;

    float acc[8][8];
    #pragma unroll
    for (int i = 0; i < 8; i++)
        #pragma unroll
        for (int j = 0; j < 8; j++) acc[i][j] = 0.0f;

    for (int k0 = 0; k0 < K_DIM; k0 += BK) {
        float4 a4 = *(const float4*)(Aptr + k0);
        float4 w4 = *(const float4*)(Wptr + k0);
        __syncthreads();   // previous tile fully consumed
        As[lcol + 0][lrow] = a4.x;
        As[lcol + 1][lrow] = a4.y;
        As[lcol + 2][lrow] = a4.z;
        As[lcol + 3][lrow] = a4.w;
        Bs[lcol + 0][lrow] = w4.x;
        Bs[lcol + 1][lrow] = w4.y;
        Bs[lcol + 2][lrow] = w4.z;
        Bs[lcol + 3][lrow] = w4.w;
        __syncthreads();

        #pragma unroll
        for (int k = 0; k < BK; k++) {
            float ra[8], rb[8];
            #pragma unroll
            for (int i = 0; i < 8; i++) ra[i] = As[k][tr * 8 + i];
            #pragma unroll
            for (int j = 0; j < 8; j++) rb[j] = Bs[k][tc * 8 + j];
            #pragma unroll
            for (int i = 0; i < 8; i++)
                #pragma unroll
                for (int j = 0; j < 8; j++)
                    acc[i][j] = fmaf(ra[i], rb[j], acc[i][j]);
        }
    }

    // Epilogue: add bias, write to scratch
    float bv[8];
    #pragma unroll
    for (int j = 0; j < 8; j++) bv[j] = bias[bn + tc * 8 + j];

    #pragma unroll
    for (int i = 0; i < 8; i++) {
        const int row = bm + tr * 8 + i;
        float* Crow = g_cur1 + (size_t)row * H_DIM + bn + tc * 8;
        #pragma unroll
        for (int j = 0; j < 8; j++)
            Crow[j] = acc[i][j] + bv[j];
    }
}

// ---------------------------------------------------------------------------
// Recurrent LIF dynamics: one CTA per batch element, 256 threads.
// Thread owns 4 hidden neurons (mem1/spk1 in regs, w2 column slice in regs).
// cur2 = spk1 @ w2^T reduced via warp shuffles + one smem round per step.
// ---------------------------------------------------------------------------
__global__ __launch_bounds__(256) void recurrent_kernel(
    const float* __restrict__ w2,      // [O, H]
    const float* __restrict__ b2,      // [O]
    float* __restrict__ out_spk,       // [B, T, O]
    float* __restrict__ out_mem)       // [B, T, O]
{
    const int b    = blockIdx.x;
    const int tid  = threadIdx.x;
    const int warp = tid >> 5;
    const int lane = tid & 31;

    __shared__ float partial[2][8][O_DIM];

    // w2 slice for this thread's 4 hidden units (h = i*256 + tid)
    float w2r[4][O_DIM];
    #pragma unroll
    for (int i = 0; i < 4; i++)
        #pragma unroll
        for (int o = 0; o < O_DIM; o++)
            w2r[i][o] = w2[o * H_DIM + i * 256 + tid];

    float mem1[4] = {0.f, 0.f, 0.f, 0.f};
    float spk1[4] = {0.f, 0.f, 0.f, 0.f};
    float mem2 = 0.f, spk2 = 0.f, bias2 = 0.f;
    if (warp == 0 && lane < O_DIM) bias2 = b2[lane];

    const float* curb = g_cur1 + (size_t)b * T_STEPS * H_DIM;

    // prefetch t=0
    float c[4];
    #pragma unroll
    for (int i = 0; i < 4; i++) c[i] = curb[i * 256 + tid];

    for (int t = 0; t < T_STEPS; t++) {
        // prefetch t+1 while computing t
        float cn[4] = {0.f, 0.f, 0.f, 0.f};
        if (t + 1 < T_STEPS) {
            const float* p = curb + (size_t)(t + 1) * H_DIM;
            #pragma unroll
            for (int i = 0; i < 4; i++) cn[i] = p[i * 256 + tid];
        }

        float acc[O_DIM];
        #pragma unroll
        for (int o = 0; o < O_DIM; o++) acc[o] = 0.0f;

        #pragma unroll
        for (int i = 0; i < 4; i++) {
            // rst equals previous-step spike (same threshold test on pre-update mem)
            mem1[i] = fmaf(BETA, mem1[i], c[i]) - spk1[i];
            spk1[i] = (mem1[i] > 1.0f) ? 1.0f : 0.0f;
            #pragma unroll
            for (int o = 0; o < O_DIM; o++)
                acc[o] = fmaf(spk1[i], w2r[i][o], acc[o]);
        }

        // intra-warp butterfly reduction of the 10 partial sums
        #pragma unroll
        for (int off = 16; off > 0; off >>= 1)
            #pragma unroll
            for (int o = 0; o < O_DIM; o++)
                acc[o] += __shfl_xor_sync(0xffffffffu, acc[o], off);

        const int par = t & 1;
        if (lane == 0) {
            #pragma unroll
            for (int o = 0; o < O_DIM; o++)
                partial[par][warp][o] = acc[o];
        }
        __syncthreads();

        if (warp == 0 && lane < O_DIM) {
            float s = bias2;
            #pragma unroll
            for (int w = 0; w < 8; w++) s += partial[par][w][lane];
            mem2 = fmaf(BETA, mem2, s) - spk2;
            spk2 = (mem2 > 1.0f) ? 1.0f : 0.0f;
            const size_t oi = ((size_t)b * T_STEPS + t) * O_DIM + lane;
            out_spk[oi] = spk2;
            out_mem[oi] = mem2;
        }

        #pragma unroll
        for (int i = 0; i < 4; i++) c[i] = cn[i];
    }
}

// ---------------------------------------------------------------------------
extern "C" void kernel_launch(void* const* d_in, const int* in_sizes, int n_in,
                              void* d_out, int out_size)
{
    const float* x  = (const float*)d_in[0];   // [B, T, I]
    const float* w1 = (const float*)d_in[1];   // [H, I]
    const float* b1 = (const float*)d_in[2];   // [H]
    const float* w2 = (const float*)d_in[3];   // [O, H]
    const float* b2 = (const float*)d_in[4];   // [O]
    float* out = (float*)d_out;                // spk2 [B,T,O] then mem2 [B,T,O]

    dim3 g1(H_DIM / 128, M_TOTAL / 128);       // (8, 200)
    gemm1_kernel<<<g1, 256>>>(x, w1, b1);

    recurrent_kernel<<<B_SIZE, 256>>>(w2, b2, out, out + (size_t)B_SIZE * T_STEPS * O_DIM);
}

// round 7
// speedup vs baseline: 1.1533x; 1.1533x over previous
#include <cuda_runtime.h>
#include <cstdint>

#define K_DIM   784
#define H_DIM   1024
#define O_DIM   10
#define B_SIZE  128
#define T_STEPS 200
#define M_TOTAL (B_SIZE * T_STEPS)   // 25600
#define BETA    0.95f

#define BMg 128
#define BNg 128
#define BKg 16
#define KTILES (K_DIM / BKg)         // 49, exact

typedef unsigned long long ull;

__device__ float    g_cur1[(size_t)M_TOTAL * H_DIM];
__device__ unsigned g_spk[(size_t)M_TOTAL * (H_DIM / 32)];
__device__ float    g_cur2[(size_t)M_TOTAL * O_DIM];

// ---------------- packed fp32x2 helpers (sm_103a FFMA2) ----------------
__device__ __forceinline__ ull ffma2(ull a, ull b, ull c) {
    ull d;
    asm("fma.rn.f32x2 %0, %1, %2, %3;" : "=l"(d) : "l"(a), "l"(b), "l"(c));
    return d;
}
__device__ __forceinline__ ull pack2(float x, float y) {
    ull d; asm("mov.b64 %0, {%1, %2};" : "=l"(d) : "f"(x), "f"(y)); return d;
}
__device__ __forceinline__ void unpack2(ull v, float& x, float& y) {
    asm("mov.b64 {%0, %1}, %2;" : "=f"(x), "=f"(y) : "l"(v));
}

// ---------------------------------------------------------------------------
// GEMM1: cur1[M,H] = x[M,K] @ w1[H,K]^T + b1.
// Pure fp32, k strictly sequential per accumulator (bitwise == cublas SGEMM
// == reference). FFMA2 packs two n-adjacent accumulator chains per instr.
// 256 threads; per-thread tile 8m x 8n (acc as 8m x 4 f32x2-pairs).
// Reg-staged double buffer: LDG next tile during compute, STS at tile start.
// ---------------------------------------------------------------------------
__global__ __launch_bounds__(256, 2) void gemm1_ffma2(
    const float* __restrict__ x, const float* __restrict__ w1,
    const float* __restrict__ bias)
{
    __shared__ float As[BKg][BMg];    // [k][m]
    __shared__ float Bs[BKg][BNg];    // [k][n]

    const int tid = threadIdx.x;
    const int tr  = tid & 15;         // m-block: rows tr*8 .. tr*8+7
    const int tc  = tid >> 4;         // n-block: cols tc*8 .. tc*8+7
    const int bm  = blockIdx.y * BMg;
    const int bn  = blockIdx.x * BNg;
    const int lr  = tid >> 1;         // load row 0..127
    const int lk  = (tid & 1) * 8;    // load k offset 0 or 8

    const float* ag = x  + (size_t)(bm + lr) * K_DIM + lk;
    const float* bg = w1 + (size_t)(bn + lr) * K_DIM + lk;

    // prologue: stage tile 0 in registers
    float4 a0 = *(const float4*)(ag);
    float4 a1 = *(const float4*)(ag + 4);
    float4 b0 = *(const float4*)(bg);
    float4 b1 = *(const float4*)(bg + 4);

    ull acc[8][4];
    #pragma unroll
    for (int i = 0; i < 8; i++)
        #pragma unroll
        for (int j = 0; j < 4; j++) acc[i][j] = 0ULL;

    for (int t = 0; t < KTILES; t++) {
        // store staged tile to smem (transposed to [k][m] / [k][n])
        As[lk + 0][lr] = a0.x; As[lk + 1][lr] = a0.y;
        As[lk + 2][lr] = a0.z; As[lk + 3][lr] = a0.w;
        As[lk + 4][lr] = a1.x; As[lk + 5][lr] = a1.y;
        As[lk + 6][lr] = a1.z; As[lk + 7][lr] = a1.w;
        Bs[lk + 0][lr] = b0.x; Bs[lk + 1][lr] = b0.y;
        Bs[lk + 2][lr] = b0.z; Bs[lk + 3][lr] = b0.w;
        Bs[lk + 4][lr] = b1.x; Bs[lk + 5][lr] = b1.y;
        Bs[lk + 6][lr] = b1.z; Bs[lk + 7][lr] = b1.w;
        __syncthreads();

        // stage next tile (latency hidden under the 16 k-steps below)
        if (t + 1 < KTILES) {
            const float* an = ag + (size_t)(t + 1) * BKg;
            const float* bn_ = bg + (size_t)(t + 1) * BKg;
            a0 = *(const float4*)(an);
            a1 = *(const float4*)(an + 4);
            b0 = *(const float4*)(bn_);
            b1 = *(const float4*)(bn_ + 4);
        }

        #pragma unroll
        for (int k = 0; k < BKg; k++) {
            const float4 av0 = *(const float4*)&As[k][tr * 8];
            const float4 av1 = *(const float4*)&As[k][tr * 8 + 4];
            const float4 bv0 = *(const float4*)&Bs[k][tc * 8];
            const float4 bv1 = *(const float4*)&Bs[k][tc * 8 + 4];

            // b pairs along n (adjacent floats -> free reinterpretation)
            ull b2[4];
            b2[0] = pack2(bv0.x, bv0.y);
            b2[1] = pack2(bv0.z, bv0.w);
            b2[2] = pack2(bv1.x, bv1.y);
            b2[3] = pack2(bv1.z, bv1.w);
            // a broadcast duplicated into both halves
            ull a2[8];
            a2[0] = pack2(av0.x, av0.x); a2[1] = pack2(av0.y, av0.y);
            a2[2] = pack2(av0.z, av0.z); a2[3] = pack2(av0.w, av0.w);
            a2[4] = pack2(av1.x, av1.x); a2[5] = pack2(av1.y, av1.y);
            a2[6] = pack2(av1.z, av1.z); a2[7] = pack2(av1.w, av1.w);

            #pragma unroll
            for (int i = 0; i < 8; i++)
                #pragma unroll
                for (int j = 0; j < 4; j++)
                    acc[i][j] = ffma2(a2[i], b2[j], acc[i][j]);
        }
        __syncthreads();
    }

    // epilogue: cur1 = acc + bias (bias added once after full k-sum, like ref)
    const int colb = bn + tc * 8;
    float bv[8];
    #pragma unroll
    for (int j = 0; j < 8; j++) bv[j] = bias[colb + j];

    #pragma unroll
    for (int i = 0; i < 8; i++) {
        const int row = bm + tr * 8 + i;
        float r[8];
        #pragma unroll
        for (int j = 0; j < 4; j++) {
            float lo, hi;
            unpack2(acc[i][j], lo, hi);
            r[j * 2]     = lo + bv[j * 2];
            r[j * 2 + 1] = hi + bv[j * 2 + 1];
        }
        float* dst = g_cur1 + (size_t)row * H_DIM + colb;
        *(float4*)(dst)     = make_float4(r[0], r[1], r[2], r[3]);
        *(float4*)(dst + 4) = make_float4(r[4], r[5], r[6], r[7]);
    }
}

// ---------------------------------------------------------------------------
// Phase A: mem1 scan, one thread per (b,h); bitwise fma chain; ballot bitmask.
// ---------------------------------------------------------------------------
__global__ __launch_bounds__(256) void phaseA_kernel() {
    const int gid = blockIdx.x * 256 + threadIdx.x;
    const int b = gid >> 10;
    const int h = gid & 1023;
    const int lane = threadIdx.x & 31;

    const float* cp = g_cur1 + (size_t)b * T_STEPS * H_DIM + h;
    unsigned* sp = g_spk + (size_t)b * T_STEPS * 32 + (h >> 5);

    float mem = 0.f, spk = 0.f;
    float c = cp[0];
    for (int t = 0; t < T_STEPS; t++) {
        float cn = (t + 1 < T_STEPS) ? cp[(size_t)(t + 1) * H_DIM] : 0.f;
        mem = fmaf(BETA, mem, c) - spk;
        spk = (mem > 1.0f) ? 1.0f : 0.0f;
        unsigned bal = __ballot_sync(0xffffffffu, mem > 1.0f);
        if (lane == 0) sp[(size_t)t * 32] = bal;
        c = cn;
    }
}

// ---------------------------------------------------------------------------
// Phase B: cur2[m][o] = sum_h spk[m][h]*w2[o][h], h strictly sequential.
// ---------------------------------------------------------------------------
__global__ __launch_bounds__(256) void phaseB_kernel(const float* __restrict__ w2) {
    __shared__ float w2s[H_DIM * O_DIM];
    for (int i = threadIdx.x; i < H_DIM * O_DIM; i += 256) {
        const int o = i / H_DIM, h = i % H_DIM;
        w2s[h * O_DIM + o] = w2[i];
    }
    __syncthreads();

    const int warp = blockIdx.x * 8 + (threadIdx.x >> 5);
    const int row  = warp * 32 + (threadIdx.x & 31);

    float acc[O_DIM];
    #pragma unroll
    for (int o = 0; o < O_DIM; o++) acc[o] = 0.f;

    const unsigned* sw = g_spk + (size_t)row * 32;
    for (int wb = 0; wb < 32; wb++) {
        const unsigned bits = sw[wb];
        #pragma unroll 8
        for (int j = 0; j < 32; j++) {
            const float f = ((bits >> j) & 1u) ? 1.0f : 0.0f;
            const float* wp = &w2s[(wb * 32 + j) * O_DIM];
            #pragma unroll
            for (int o = 0; o < O_DIM; o++)
                acc[o] = fmaf(f, wp[o], acc[o]);
        }
    }
    float* op = g_cur2 + (size_t)row * O_DIM;
    #pragma unroll
    for (int o = 0; o < O_DIM; o++) op[o] = acc[o];
}

// ---------------------------------------------------------------------------
// Phase C: mem2 scan per (b,o).
// ---------------------------------------------------------------------------
__global__ void phaseC_kernel(const float* __restrict__ b2,
                              float* __restrict__ out_spk,
                              float* __restrict__ out_mem) {
    const int b = blockIdx.x;
    const int lane = threadIdx.x;
    if (lane >= O_DIM) return;

    const float bias = b2[lane];
    const float* cp = g_cur2 + (size_t)b * T_STEPS * O_DIM + lane;
    float* os = out_spk + (size_t)b * T_STEPS * O_DIM + lane;
    float* om = out_mem + (size_t)b * T_STEPS * O_DIM + lane;

    float mem = 0.f, spk = 0.f;
    for (int t0 = 0; t0 < T_STEPS; t0 += 8) {
        float c[8];
        #pragma unroll
        for (int i = 0; i < 8; i++) c[i] = cp[(size_t)(t0 + i) * O_DIM];
        #pragma unroll
        for (int i = 0; i < 8; i++) {
            mem = fmaf(BETA, mem, c[i] + bias) - spk;
            spk = (mem > 1.0f) ? 1.0f : 0.0f;
            os[(size_t)(t0 + i) * O_DIM] = spk;
            om[(size_t)(t0 + i) * O_DIM] = mem;
        }
    }
}

// ---------------------------------------------------------------------------
extern "C" void kernel_launch(void* const* d_in, const int* in_sizes, int n_in,
                              void* d_out, int out_size)
{
    const float* x  = (const float*)d_in[0];
    const float* w1 = (const float*)d_in[1];
    const float* b1 = (const float*)d_in[2];
    const float* w2 = (const float*)d_in[3];
    const float* b2 = (const float*)d_in[4];
    float* out = (float*)d_out;

    dim3 gg(H_DIM / BNg, M_TOTAL / BMg);        // (8, 200)
    gemm1_ffma2<<<gg, 256>>>(x, w1, b1);

    phaseA_kernel<<<(B_SIZE * H_DIM) / 256, 256>>>();
    phaseB_kernel<<<M_TOTAL / 256, 256>>>(w2);
    phaseC_kernel<<<B_SIZE, 32>>>(b2, out, out + (size_t)B_SIZE * T_STEPS * O_DIM);
}